// round 1
// baseline (speedup 1.0000x reference)
#include <cuda_runtime.h>

#define NIMG 1024          // B*R = 16*64
#define KC_THREADS 352

// ---- scratch (static device arrays: no allocation allowed) ----
__device__ float g_pooled1[NIMG * 64 * 30 * 30];   // conv1+pool1 output, [img][c][30][30]
__device__ int   g_bounds[NIMG][2][4];             // per pair, per channel: jx1 jx2 iy1 iy2
__device__ float g_w2t[64 * 25 * 32];              // conv2 weights transposed: [c][dy][dx][oc]

// ---------------- packed f32x2 helpers ----------------
__device__ __forceinline__ unsigned long long fma2(unsigned long long a,
                                                   unsigned long long b,
                                                   unsigned long long c) {
    unsigned long long d;
    asm("fma.rn.f32x2 %0, %1, %2, %3;" : "=l"(d) : "l"(a), "l"(b), "l"(c));
    return d;
}
__device__ __forceinline__ unsigned long long dup2(float v) {
    unsigned long long d;
    asm("mov.b64 %0, {%1, %1};" : "=l"(d) : "f"(v));
    return d;
}
__device__ __forceinline__ float2 u2f(unsigned long long u) {
    float2 f;
    asm("mov.b64 {%0, %1}, %2;" : "=f"(f.x), "=f"(f.y) : "l"(u));
    return f;
}

// ---------------- Kernel A: integer rect bounds per (pair, channel) ----------------
// Replicates reference float math exactly: x1=(b-ux1)/uw*64, pixel active iff
// (j+0.5 >= x1) && (j+0.5 <= x2). Bounds extracted by evaluating the comparisons.
__global__ void k_bounds(const float* __restrict__ bboxes,
                         const int*   __restrict__ pairs) {
    int n = blockIdx.x * blockDim.x + threadIdx.x;
    if (n >= NIMG) return;
    int b  = n >> 6;                 // R = 64
    int p0 = pairs[n * 2 + 0];
    int p1 = pairs[n * 2 + 1];
    const float* B0 = bboxes + (b * 32 + p0) * 4;
    const float* B1 = bboxes + (b * 32 + p1) * 4;
    float bx1[2] = {B0[0], B1[0]}, by1[2] = {B0[1], B1[1]};
    float bx2[2] = {B0[2], B1[2]}, by2[2] = {B0[3], B1[3]};
    float ux1 = fminf(bx1[0], bx1[1]), uy1 = fminf(by1[0], by1[1]);
    float ux2 = fmaxf(bx2[0], bx2[1]), uy2 = fmaxf(by2[0], by2[1]);
    float uw = fmaxf(ux2 - ux1, 1e-6f), uh = fmaxf(uy2 - uy1, 1e-6f);
    for (int c = 0; c < 2; ++c) {
        float x1 = (bx1[c] - ux1) / uw * 64.0f;
        float y1 = (by1[c] - uy1) / uh * 64.0f;
        float x2 = (bx2[c] - ux1) / uw * 64.0f;
        float y2 = (by2[c] - uy1) / uh * 64.0f;
        int jlo = 64, jhi = -1, ilo = 64, ihi = -1;
        for (int k = 0; k < 64; ++k) {
            float f = (float)k + 0.5f;
            if (f >= x1 && f <= x2) { if (k < jlo) jlo = k; jhi = k; }
            if (f >= y1 && f <= y2) { if (k < ilo) ilo = k; ihi = k; }
        }
        g_bounds[n][c][0] = jlo; g_bounds[n][c][1] = jhi;
        g_bounds[n][c][2] = ilo; g_bounds[n][c][3] = ihi;
    }
}

// ---------------- Kernel A2: transpose conv2 weights to [c][dy][dx][oc] ----------------
__global__ void k_wtrans(const float* __restrict__ w2) {
    int i = blockIdx.x * blockDim.x + threadIdx.x;
    if (i >= 64 * 25 * 32) return;
    int oc = i & 31;
    int rest = i >> 5;
    int dx = rest % 5;
    int r2 = rest / 5;
    int dy = r2 % 5;
    int c  = r2 / 5;
    g_w2t[i] = w2[((oc * 64 + c) * 5 + dy) * 5 + dx];
}

// ---------------- Kernel B: conv1 + bias + maxpool2 via 2D weight prefix sums ----------------
// conv1 out[o,i,j] = b1[o] + sum_c rectsum(P[o][c], clipped window). Exact (reassociated sums).
__global__ void k_conv1pool(const float* __restrict__ w1,
                            const float* __restrict__ b1) {
    __shared__ float P[64 * 2 * 36];     // [o][c][6][6] prefix: P[a][b]=sum_{dy<a,dx<b} w
    __shared__ float bias[64];
    __shared__ int wy[2][60], wx[2][60]; // packed window codes: lo | (hiEx<<4)
    int img = blockIdx.x, t = threadIdx.x;

    if (t < 128) {
        int o = t >> 1, c = t & 1;
        float wloc[25];
#pragma unroll
        for (int k = 0; k < 25; ++k) wloc[k] = w1[(o * 2 + c) * 25 + k];
        float* Pt = &P[(o * 2 + c) * 36];
#pragma unroll
        for (int bb = 0; bb < 6; ++bb) Pt[bb] = 0.0f;
#pragma unroll
        for (int a = 1; a < 6; ++a) {
            Pt[a * 6] = 0.0f;
            float rs = 0.0f;
#pragma unroll
            for (int bb = 1; bb < 6; ++bb) {
                rs += wloc[(a - 1) * 5 + (bb - 1)];
                Pt[a * 6 + bb] = Pt[(a - 1) * 6 + bb] + rs;
            }
        }
    }
    if (t < 64) bias[t] = b1[t];
    if (t < 240) {
        int c = t & 1;
        int rest = t >> 1;
        int pos = rest % 60;
        int dim = rest / 60;                     // 0 = x codes, 1 = y codes
        int lo = g_bounds[img][c][dim ? 2 : 0];
        int hi = g_bounds[img][c][dim ? 3 : 1];
        int l = lo - pos;      l = max(0, min(5, l));
        int h = hi + 1 - pos;  h = max(l, min(5, h));   // exclusive upper, empty-safe
        int code = l | (h << 4);
        if (dim) wy[c][pos] = code; else wx[c][pos] = code;
    }
    __syncthreads();

    float* outp = g_pooled1 + (size_t)img * 57600;
    for (int idx = t; idx < 57600; idx += 256) {
        int o = idx / 900;
        int r = idx - o * 900;
        int I = r / 30, J = r - I * 30;
        const float* P0 = &P[o * 72];
        const float* P1 = P0 + 36;
        float bo = bias[o];
        float m = -1e30f;
#pragma unroll
        for (int iy = 0; iy < 2; ++iy) {
            int i = 2 * I + iy;
            int cy0 = wy[0][i], cy1 = wy[1][i];
#pragma unroll
            for (int jx = 0; jx < 2; ++jx) {
                int j = 2 * J + jx;
                int cx0 = wx[0][j], cx1 = wx[1][j];
                float v = bo;
                {
                    int yl = cy0 & 15, yh = cy0 >> 4, xl = cx0 & 15, xh = cx0 >> 4;
                    v += P0[yh * 6 + xh] - P0[yl * 6 + xh] - P0[yh * 6 + xl] + P0[yl * 6 + xl];
                }
                {
                    int yl = cy1 & 15, yh = cy1 >> 4, xl = cx1 & 15, xh = cx1 >> 4;
                    v += P1[yh * 6 + xh] - P1[yl * 6 + xh] - P1[yh * 6 + xl] + P1[yl * 6 + xl];
                }
                m = fmaxf(m, v);
            }
        }
        outp[idx] = m;
    }
}

// ---------------- Kernel C: conv2 + bias + maxpool2 + mean + fc + relu (fused) ----------------
// One CTA per image. Shared: input half (32ch x 30x32 padded) + weights (32ch x 25 x 32oc).
// Each active thread (338 of 352): 1 out row x 2 out cols (one pool pair) x 32 out channels,
// accumulated as 32 packed f32x2 registers via fma.rn.f32x2 (2x fp32 rate on sm_103a).
__global__ void __launch_bounds__(KC_THREADS, 1)
k_conv2tail(const float* __restrict__ b2,
            const float* __restrict__ fcw,
            const float* __restrict__ fcb,
            float* __restrict__ out) {
    extern __shared__ float sh[];
    float* ins = sh;             // 32 * 30 * 32 = 30720 floats (x-stride padded to 32)
    float* ws  = sh + 30720;     // 32 * 25 * 32 = 25600 floats, [cc][dy][dx][oc]
    __shared__ float sfeat[32];
    __shared__ float sb2[32];

    int img = blockIdx.x, t = threadIdx.x;
    if (t < 32) sb2[t] = b2[t];
    bool act = t < 338;
    int orow = t / 13;
    int ocl  = t - orow * 13;
    int j0   = 2 * ocl;

    unsigned long long acc[32];
#pragma unroll
    for (int q = 0; q < 32; ++q) acc[q] = 0ull;   // packed (0.f, 0.f)

    for (int cg = 0; cg < 2; ++cg) {
        __syncthreads();   // previous chunk's compute done before overwrite
        // load 32-channel input chunk (coalesced float2, repack to stride-32 rows)
        const float2* src = (const float2*)(g_pooled1 + (size_t)img * 57600 + cg * 28800);
        for (int i2 = t; i2 < 14400; i2 += KC_THREADS) {
            int s = i2 << 1;
            int cc = s / 900;
            int r  = s - cc * 900;
            int y  = r / 30;
            int x  = r - y * 30;
            *(float2*)(ins + cc * 960 + y * 32 + x) = src[i2];
        }
        // load weight chunk (contiguous, float4)
        const float4* wsrc = (const float4*)(g_w2t + cg * 25600);
        float4* wdst = (float4*)ws;
        for (int i4 = t; i4 < 6400; i4 += KC_THREADS) wdst[i4] = wsrc[i4];
        __syncthreads();

        if (act) {
            for (int cc = 0; cc < 32; ++cc) {
                const float* inc = ins + cc * 960 + orow * 32 + j0;
                const ulonglong2* wcc = (const ulonglong2*)(ws + cc * 800);
#pragma unroll 1
                for (int dy = 0; dy < 5; ++dy) {
                    const float2* vp = (const float2*)(inc + dy * 32);
                    float2 va = vp[0], vb = vp[1], vc = vp[2];
                    unsigned long long dva[6];
                    dva[0] = dup2(va.x); dva[1] = dup2(va.y);
                    dva[2] = dup2(vb.x); dva[3] = dup2(vb.y);
                    dva[4] = dup2(vc.x); dva[5] = dup2(vc.y);
                    const ulonglong2* wrow = wcc + dy * 40;   // 5 dx * 8 vec each
#pragma unroll
                    for (int dx = 0; dx < 5; ++dx) {
#pragma unroll
                        for (int q = 0; q < 8; ++q) {
                            ulonglong2 w = wrow[dx * 8 + q];
                            acc[2 * q]          = fma2(dva[dx],     w.x, acc[2 * q]);
                            acc[2 * q + 1]      = fma2(dva[dx],     w.y, acc[2 * q + 1]);
                            acc[16 + 2 * q]     = fma2(dva[dx + 1], w.x, acc[16 + 2 * q]);
                            acc[16 + 2 * q + 1] = fma2(dva[dx + 1], w.y, acc[16 + 2 * q + 1]);
                        }
                    }
                }
            }
        }
    }

    // ---- pool2 (2x2 max) + mean(13x13) + conv2 bias ----
    __syncthreads();
    float* red = ins;   // reuse, [338][32]
    if (act) {
#pragma unroll
        for (int p = 0; p < 16; ++p) {
            float2 a = u2f(acc[p]);        // px0, channels 2p / 2p+1
            float2 b = u2f(acc[16 + p]);   // px1
            red[t * 32 + 2 * p]     = fmaxf(a.x, b.x);   // column-pair max
            red[t * 32 + 2 * p + 1] = fmaxf(a.y, b.y);
        }
    }
    __syncthreads();
    if (act && (orow & 1) == 0) {
#pragma unroll
        for (int oc = 0; oc < 32; ++oc)
            red[t * 32 + oc] = fmaxf(red[t * 32 + oc], red[(t + 13) * 32 + oc]);  // row-pair max
    }
    __syncthreads();
    if (t < 32) {
        float s = 0.0f;
        for (int I = 0; I < 13; ++I)
            for (int J = 0; J < 13; ++J)
                s += red[(2 * I * 13 + J) * 32 + t];
        sfeat[t] = s * (1.0f / 169.0f) + sb2[t];   // max commutes with +bias; mean adds bias
    }
    __syncthreads();

    // ---- fc 32 -> 512 + relu ----
    for (int o = t; o < 512; o += KC_THREADS) {
        const float4* wv = (const float4*)(fcw + o * 32);
        float s = fcb[o];
#pragma unroll
        for (int q = 0; q < 8; ++q) {
            float4 w = wv[q];
            s += w.x * sfeat[q * 4 + 0] + w.y * sfeat[q * 4 + 1]
               + w.z * sfeat[q * 4 + 2] + w.w * sfeat[q * 4 + 3];
        }
        out[(size_t)img * 512 + o] = fmaxf(s, 0.0f);
    }
}

// ---------------- launch ----------------
extern "C" void kernel_launch(void* const* d_in, const int* in_sizes, int n_in,
                              void* d_out, int out_size) {
    const float* bboxes = (const float*)d_in[0];
    // d_in[1] num_obj, d_in[2] num_relation: unused by reference computation
    const int*   pairs  = (const int*)d_in[3];
    const float* w1     = (const float*)d_in[4];
    const float* b1     = (const float*)d_in[5];
    const float* w2     = (const float*)d_in[6];
    const float* b2     = (const float*)d_in[7];
    const float* fcw    = (const float*)d_in[8];
    const float* fcb    = (const float*)d_in[9];
    float* out = (float*)d_out;

    k_bounds<<<4, 256>>>(bboxes, pairs);
    k_wtrans<<<50, 1024>>>(w2);
    k_conv1pool<<<NIMG, 256>>>(w1, b1);

    static const int kSmem = (30720 + 25600) * 4;   // 225,280 B
    cudaFuncSetAttribute(k_conv2tail, cudaFuncAttributeMaxDynamicSharedMemorySize, kSmem);
    k_conv2tail<<<NIMG, KC_THREADS, kSmem>>>(b2, fcw, fcb, out);
}